// round 12
// baseline (speedup 1.0000x reference)
#include <cuda_runtime.h>

// B=64, NIN=512, H1=H2=1024, NOUT=512, COND=64, FC=1
// out[b,o] = sum_i sigmoid(f1[b,i]*f2[b,o]) * (m*W)[o,i] * x[b,i]
// sigmoid(z) = 0.5 + 0.5*tanh(z/2); 1/2 folded into f2.
//
// MADE-mask sparsity: hidden dims sorted by degree so every mask row's active
// inputs form a prefix; row lengths monotone; dead CTA tiles exit.
// Fine-grained tiling (32 o x 8 batches x 16 i per CTA) maximizes live-CTA
// concurrency — the empirically binding resource (R7-R11).

// ---------------- device scratch ----------------
__device__ float g_MWp0[1024 * 512];    // [o'][i]   layer0 (inputs natural)
__device__ float g_MWp1[1024 * 1024];   // [o'][i']  layer1 (both sorted)
__device__ float g_MWp2[512 * 1024];    // [o][i']   layer2 (outputs natural)
__device__ float g_f1a[3 * 64 * 1024];  // f1 per layer, slot stride 65536
__device__ float g_f2a[3 * 64 * 1024];  // 0.5*f2 per layer, slot stride 65536
__device__ float g_h1[65536];           // sorted-h1 space
__device__ float g_h2[65536];           // sorted-h2 space
__device__ int   g_rs0[1024];           // rowsum(mask0) = d1
__device__ int   g_rs1[1024];           // rowsum(mask1) per natural h2
__device__ int   g_rs2[512];            // rowsum(mask2) (monotone in o)
__device__ int   g_d2[1024];            // 512 - colsum(mask2)
__device__ int   g_pos1[1024], g_perm1[1024], g_L0p[1024];
__device__ int   g_pos2[1024], g_perm2[1024], g_L1p[1024];
__device__ int   g_idp[1024];           // identity positions

__device__ __forceinline__ float tanh_fast(float x) {
    float r;
    asm("tanh.approx.f32 %0, %1;" : "=f"(r) : "f"(x));
    return r;
}
__device__ __forceinline__ unsigned long long pack2(float lo, float hi) {
    unsigned long long r;
    asm("mov.b64 %0, {%1, %2};" : "=l"(r) : "f"(lo), "f"(hi));
    return r;
}
__device__ __forceinline__ void unpack2(float& lo, float& hi, unsigned long long v) {
    asm("mov.b64 {%0, %1}, %2;" : "=f"(lo), "=f"(hi) : "l"(v));
}
__device__ __forceinline__ unsigned long long mul2(unsigned long long a, unsigned long long b) {
    unsigned long long r;
    asm("mul.rn.f32x2 %0, %1, %2;" : "=l"(r) : "l"(a), "l"(b));
    return r;
}
__device__ __forceinline__ unsigned long long fma2(unsigned long long a, unsigned long long b,
                                                   unsigned long long c) {
    unsigned long long r;
    asm("fma.rn.f32x2 %0, %1, %2, %3;" : "=l"(r) : "l"(a), "l"(b), "l"(c));
    return r;
}

// ---------------- phase 1: mask sums + zero + identity ----------------
// grid: [0,320) rowsums ; [320,352) d2 colsums ; [352,512) zero ; [512,516) id
__global__ void __launch_bounds__(256) phase1_kernel(
    const float* __restrict__ mask0, const float* __restrict__ mask1,
    const float* __restrict__ mask2, float4* __restrict__ outz) {
    int bid = blockIdx.x, tid = threadIdx.x;
    if (bid < 320) {
        int wrow = bid * 8 + (tid >> 5);      // 0..2559
        int lane = tid & 31;
        const float* row; int len; int* dst; int r;
        if (wrow < 1024)      { r = wrow;        row = mask0 + r * 512;  len = 512;  dst = g_rs0; }
        else if (wrow < 2048) { r = wrow - 1024; row = mask1 + r * 1024; len = 1024; dst = g_rs1; }
        else                  { r = wrow - 2048; row = mask2 + r * 1024; len = 1024; dst = g_rs2; }
        float s = 0.f;
        for (int c = lane; c < len; c += 32) s += row[c];
#pragma unroll
        for (int d = 16; d > 0; d >>= 1) s += __shfl_xor_sync(0xffffffffu, s, d);
        if (lane == 0) dst[r] = (int)(s + 0.5f);
        return;
    }
    if (bid < 352) {
        // d2 colsums: CTA c covers columns [32c, 32c+32); warp w sums rows [64w, 64w+64)
        __shared__ int part[8][32];
        int c = bid - 320;
        int w = tid >> 5, lane = tid & 31;
        int col = c * 32 + lane;
        int acc = 0;
        for (int r = 0; r < 64; ++r)
            acc += (int)(mask2[(w * 64 + r) * 1024 + col] + 0.5f);
        part[w][lane] = acc;
        __syncthreads();
        if (w == 0) {
            int s = 0;
#pragma unroll
            for (int q = 0; q < 8; ++q) s += part[q][lane];
            g_d2[col] = 512 - s;
        }
        return;
    }
    if (bid < 512) {
        int idx = (bid - 352) * 256 + tid;    // 40960 float4s
        float4 z = make_float4(0.f, 0.f, 0.f, 0.f);
        if (idx < 16384)      ((float4*)g_h1)[idx] = z;
        else if (idx < 32768) ((float4*)g_h2)[idx - 16384] = z;
        else if (idx < 40960) outz[idx - 32768] = z;
        return;
    }
    {
        int j = (bid - 512) * 256 + tid;
        if (j < 1024) g_idp[j] = j;
    }
}

// ---------------- phase 2: parallel deterministic rank sort ----------------
// grid 256 x 256thr; warp per element. CTAs [0,128): key=rs0 -> pos1/perm1/L0p.
// CTAs [128,256): key=d2 -> pos2/perm2/L1p.
__global__ void __launch_bounds__(256) phase2_kernel() {
    int w = threadIdx.x >> 5, lane = threadIdx.x & 31;
    bool second = blockIdx.x >= 128;
    int t = (blockIdx.x & 127) * 8 + w;   // 0..1023
    const int* keys = second ? g_d2 : g_rs0;
    int k = keys[t];
    int r = 0;
    for (int h = lane; h < 1024; h += 32) {
        int kh = keys[h];
        r += (kh < k) || (kh == k && h < t);
    }
#pragma unroll
    for (int d = 16; d > 0; d >>= 1) r += __shfl_xor_sync(0xffffffffu, r, d);
    if (lane == 0) {
        if (!second) {
            g_pos1[t] = r;
            g_perm1[r] = t;
            g_L0p[r] = k;              // sorted row length = its d1
        } else {
            g_pos2[t] = r;
            g_perm2[r] = t;
            g_L1p[r] = g_rs1[t];       // prefix length in sorted-d1 input space
        }
    }
}

// ---------------- phase 3: permuted MW (row-major) + cond GEMVs --------------
// grid: [0,512) L0 direct ; [512,640) L1 smem-permute ; [640,704) L2 smem-permute
//       [704,2240) cond GEMVs (6*256)
__global__ void __launch_bounds__(256) phase3_kernel(
    const float* __restrict__ mask0, const float* __restrict__ W0,
    const float* __restrict__ mask1, const float* __restrict__ W1,
    const float* __restrict__ mask2, const float* __restrict__ W2,
    const float* __restrict__ u,
    const float* __restrict__ cw0, const float* __restrict__ cb0,
    const float* __restrict__ cw1, const float* __restrict__ cb1,
    const float* __restrict__ cw2, const float* __restrict__ cb2,
    const float* __restrict__ cw3, const float* __restrict__ cb3,
    const float* __restrict__ cw4, const float* __restrict__ cb4,
    const float* __restrict__ cw5, const float* __restrict__ cb5) {
    __shared__ float sh[9216];   // 8 rows x 1024 + 1024-int perm (aliased) / us
    int bid = blockIdx.x, tid = threadIdx.x;

    if (bid < 512) {
        // L0: MWp0[o'][i] = (mask0*W0)[perm1[o']][i] — fully coalesced
        int idx = bid * 256 + tid;           // f4 index: [1024 rows][128 f4]
        int o = idx >> 7, i4 = idx & 127;
        int srow = g_perm1[o];
        float4 mv = ((const float4*)(mask0 + srow * 512))[i4];
        float4 wv = ((const float4*)(W0 + srow * 512))[i4];
        ((float4*)g_MWp0)[idx] =
            make_float4(mv.x * wv.x, mv.y * wv.y, mv.z * wv.z, mv.w * wv.w);
        return;
    }
    if (bid < 704) {
        // L1 / L2: row gather (coalesced) + column permute via smem
        bool isL1 = bid < 640;
        int rb = isL1 ? (bid - 512) * 8 : (bid - 640) * 8;
        float* rowbuf = sh;
        int* ps = (int*)(sh + 8192);
        const int* permC = isL1 ? g_perm1 : g_perm2;   // column permutation
        for (int k = tid; k < 1024; k += 256) ps[k] = permC[k];
        for (int k = tid; k < 2048; k += 256) {        // 8 rows x 256 f4
            int r = k >> 8, i4 = k & 255;
            int srow = isL1 ? g_perm2[rb + r] : (rb + r);
            const float* mrow = (isL1 ? mask1 : mask2) + (size_t)srow * 1024;
            const float* wrow = (isL1 ? W1 : W2) + (size_t)srow * 1024;
            float4 mv = ((const float4*)mrow)[i4];
            float4 wv = ((const float4*)wrow)[i4];
            *(float4*)&rowbuf[r * 1024 + i4 * 4] =
                make_float4(mv.x * wv.x, mv.y * wv.y, mv.z * wv.z, mv.w * wv.w);
        }
        __syncthreads();
        float* dst = isL1 ? g_MWp1 : g_MWp2;
        for (int k = tid; k < 8192; k += 256) {
            int r = k >> 10, i = k & 1023;
            dst[(size_t)(rb + r) * 1024 + i] = rowbuf[r * 1024 + ps[i]];
        }
        return;
    }
    // ---- cond GEMVs with permuted destinations ----
    {
        float* us = sh;  // 64*65 floats
        int cbid = bid - 704;
        int jblk = cbid & 255;
        int which = cbid >> 8;  // 0..5
        for (int k = tid; k < 64 * 64; k += 256)
            us[(k >> 6) * 65 + (k & 63)] = u[k];
        __syncthreads();

        const float* w; const float* bias; const int* pos;
        int J; float scale; float* dstp;
        switch (which) {
            case 0:  w = cw0; bias = cb0; J = 512;  scale = 1.0f; dstp = g_f1a;          pos = g_idp;  break;
            case 1:  w = cw1; bias = cb1; J = 1024; scale = 0.5f; dstp = g_f2a;          pos = g_pos1; break;
            case 2:  w = cw2; bias = cb2; J = 1024; scale = 1.0f; dstp = g_f1a + 65536;  pos = g_pos1; break;
            case 3:  w = cw3; bias = cb3; J = 1024; scale = 0.5f; dstp = g_f2a + 65536;  pos = g_pos2; break;
            case 4:  w = cw4; bias = cb4; J = 1024; scale = 1.0f; dstp = g_f1a + 131072; pos = g_pos2; break;
            default: w = cw5; bias = cb5; J = 512;  scale = 0.5f; dstp = g_f2a + 131072; pos = g_idp;  break;
        }
        int b = tid & 63;
        int jj = tid >> 6;
        int j = jblk * 4 + jj;
        if (j >= J) return;
        const float* wr = w + j * 64;
        float acc = 0.0f;
#pragma unroll
        for (int c = 0; c < 64; ++c)
            acc = __fmaf_rn(wr[c], us[b * 65 + c], acc);
        dstp[b * J + pos[j]] = (acc + bias[j]) * scale;
    }
}

// ---------------- main layer kernel ----------------
// CTA = 32 outputs x 8 batches (4 f32x2 pairs) x ISEG=16 inputs.
// Thread: output oBase+tx, single batch-pair pr=ty; full compile-time unroll.
// MW zeros beyond the mask prefix make boundary-tile extra iterations exact 0;
// fully-dead tiles exit early. grid (O/32, 8, NS); split-K via atomicAdd (RED).
template <int I, int O, int NS>
__global__ void __launch_bounds__(128) layer_kernel(
    const float* __restrict__ xsrc,
    const float* __restrict__ f1, const float* __restrict__ f2,
    const float* __restrict__ MW, const int* __restrict__ Lp,
    float* __restrict__ hdst) {
    constexpr int ISEG = I / NS;      // 16
    constexpr int NPAIRS = ISEG / 2;  // 8

    __shared__ float2 MW2s[NPAIRS][32];            // [ii-pair][o]
    __shared__ unsigned long long fps[4][ISEG];    // packed f1 batch-pairs
    __shared__ unsigned long long xps[4][ISEG];    // packed x  batch-pairs

    int tx = threadIdx.x, ty = threadIdx.y;
    int tid = ty * 32 + tx;
    int oBase = blockIdx.x * 32;
    int bBase = blockIdx.y * 8;
    int iBase = blockIdx.z * ISEG;

    if (iBase >= Lp[oBase + 31]) return;  // rows ascending => whole tile masked

    // stage MW as ii-pairs: 32 o x 4 float4, exactly one per thread
    {
        int o = tid >> 2, i4 = tid & 3;   // ISEG/4 = 4
        float4 v = *(const float4*)(MW + (size_t)(oBase + o) * I + iBase + i4 * 4);
        MW2s[i4 * 2 + 0][o] = make_float2(v.x, v.y);
        MW2s[i4 * 2 + 1][o] = make_float2(v.z, v.w);
    }
    // stage packed (f1, x): 4 pairs x 16 ii x 2 arrays = 128 items, one/thread
    {
        int which = tid >> 6;             // 0: f1, 1: x
        int k = tid & 63;
        int pr = k >> 4, ii = k & 15;
        int b = bBase + 2 * pr;
        int gi = iBase + ii;
        const float* src = which ? xsrc : f1;
        unsigned long long v = pack2(src[b * I + gi], src[(b + 1) * I + gi]);
        (which ? xps : fps)[pr][ii] = v;
    }

    int o = oBase + tx;
    int b0 = bBase + 2 * ty;
    unsigned long long f2p = pack2(f2[b0 * O + o], f2[(b0 + 1) * O + o]);
    unsigned long long acc = 0ULL;
    const unsigned long long H = 0x3f0000003f000000ULL;  // {0.5f, 0.5f}

    __syncthreads();

#pragma unroll
    for (int p = 0; p < NPAIRS; ++p) {
        float2 mw = MW2s[p][tx];                       // one LDS.64 per 2 ii
        unsigned long long mwd0 = pack2(mw.x, mw.x);
        unsigned long long mwd1 = pack2(mw.y, mw.y);
        ulonglong2 fq = *(const ulonglong2*)&fps[ty][2 * p];  // LDS.128
        ulonglong2 xq = *(const ulonglong2*)&xps[ty][2 * p];  // LDS.128
        float za, zb;
        unsigned long long z0 = mul2(fq.x, f2p);
        unpack2(za, zb, z0);
        unsigned long long t0 = pack2(tanh_fast(za), tanh_fast(zb));
        unsigned long long s0 = fma2(t0, H, H);
        acc = fma2(s0, mul2(mwd0, xq.x), acc);
        unsigned long long z1 = mul2(fq.y, f2p);
        unpack2(za, zb, z1);
        unsigned long long t1 = pack2(tanh_fast(za), tanh_fast(zb));
        unsigned long long s1 = fma2(t1, H, H);
        acc = fma2(s1, mul2(mwd1, xq.y), acc);
    }

    {
        float a0, a1;
        unpack2(a0, a1, acc);
        atomicAdd(hdst + b0 * O + o, a0);
        atomicAdd(hdst + (b0 + 1) * O + o, a1);
    }
}

extern "C" void kernel_launch(void* const* d_in, const int* in_sizes, int n_in,
                              void* d_out, int out_size) {
    const float* x     = (const float*)d_in[0];
    const float* u     = (const float*)d_in[1];
    const float* mask0 = (const float*)d_in[2];
    const float* mask1 = (const float*)d_in[3];
    const float* mask2 = (const float*)d_in[4];
    const float* W0    = (const float*)d_in[5];
    const float* W1    = (const float*)d_in[6];
    const float* W2    = (const float*)d_in[7];
    const float* a0_w  = (const float*)d_in[8];
    const float* a0_b  = (const float*)d_in[9];
    const float* b0_w  = (const float*)d_in[10];
    const float* b0_b  = (const float*)d_in[11];
    const float* a1_w  = (const float*)d_in[12];
    const float* a1_b  = (const float*)d_in[13];
    const float* b1_w  = (const float*)d_in[14];
    const float* b1_b  = (const float*)d_in[15];
    const float* a2_w  = (const float*)d_in[16];
    const float* a2_b  = (const float*)d_in[17];
    const float* b2_w  = (const float*)d_in[18];
    const float* b2_b  = (const float*)d_in[19];
    float* out = (float*)d_out;

    float* pMW0; cudaGetSymbolAddress((void**)&pMW0, g_MWp0);
    float* pMW1; cudaGetSymbolAddress((void**)&pMW1, g_MWp1);
    float* pMW2; cudaGetSymbolAddress((void**)&pMW2, g_MWp2);
    float* pf1;  cudaGetSymbolAddress((void**)&pf1, g_f1a);
    float* pf2;  cudaGetSymbolAddress((void**)&pf2, g_f2a);
    float* ph1;  cudaGetSymbolAddress((void**)&ph1, g_h1);
    float* ph2;  cudaGetSymbolAddress((void**)&ph2, g_h2);
    int* pL0;    cudaGetSymbolAddress((void**)&pL0, g_L0p);
    int* pL1;    cudaGetSymbolAddress((void**)&pL1, g_L1p);
    int* pL2;    cudaGetSymbolAddress((void**)&pL2, g_rs2);

    // 1) mask sums (rowsums + d2 colsums) + zero + identity
    phase1_kernel<<<516, 256>>>(mask0, mask1, mask2, (float4*)out);

    // 2) parallel degree-rank sort (deterministic, warp per element)
    phase2_kernel<<<256, 256>>>();

    // 3) permuted row-major MW + cond GEMVs (permuted dst)
    phase3_kernel<<<2240, 256>>>(
        mask0, W0, mask1, W1, mask2, W2, u,
        a0_w, a0_b, b0_w, b0_b,
        a1_w, a1_b, b1_w, b1_b,
        a2_w, a2_b, b2_w, b2_b);

    // 4) layer 0: x -> h1 (sorted space) ; NS=32, ISEG=16, 8192 CTAs
    layer_kernel<512, 1024, 32><<<dim3(32, 8, 32), dim3(32, 4)>>>(
        x, pf1, pf2, pMW0, pL0, ph1);

    // 5) layer 1: h1 -> h2 (sorted space) ; NS=64, ISEG=16, 16384 CTAs
    layer_kernel<1024, 1024, 64><<<dim3(32, 8, 64), dim3(32, 4)>>>(
        ph1, pf1 + 65536, pf2 + 65536, pMW1, pL1, ph2);

    // 6) layer 2: h2 -> d_out (natural rows) ; NS=64, ISEG=16, 8192 CTAs
    layer_kernel<1024, 512, 64><<<dim3(16, 8, 64), dim3(32, 4)>>>(
        ph2, pf1 + 131072, pf2 + 131072, pMW2, pL2, out);
}

// round 13
// speedup vs baseline: 1.1690x; 1.1690x over previous
#include <cuda_runtime.h>

// B=64, NIN=512, H1=H2=1024, NOUT=512, COND=64, FC=1
// out[b,o] = sum_i sigmoid(f1[b,i]*f2[b,o]) * (m*W)[o,i] * x[b,i]
// sigmoid(z) = 0.5 + 0.5*tanh(z/2); 1/2 folded into f2.
//
// MADE-mask sparsity: hidden dims sorted by degree so every mask row's active
// inputs form a prefix; row lengths monotone; dead CTA tiles exit.
// All 6 kernels chained with PDL (programmatic stream serialization):
// successor CTAs launch during predecessor tail-drain; griddepcontrol.wait
// guards every read of predecessor-produced data.

// ---------------- device scratch ----------------
__device__ float g_MWp0[1024 * 512];    // [o'][i]   layer0 (inputs natural)
__device__ float g_MWp1[1024 * 1024];   // [o'][i']  layer1 (both sorted)
__device__ float g_MWp2[512 * 1024];    // [o][i']   layer2 (outputs natural)
__device__ float g_f1a[3 * 64 * 1024];  // f1 per layer, slot stride 65536
__device__ float g_f2a[3 * 64 * 1024];  // 0.5*f2 per layer, slot stride 65536
__device__ float g_h1[65536];           // sorted-h1 space
__device__ float g_h2[65536];           // sorted-h2 space
__device__ int   g_rs0[1024];           // rowsum(mask0) = d1
__device__ int   g_rs1[1024];           // rowsum(mask1) per natural h2
__device__ int   g_rs2[512];            // rowsum(mask2) (monotone in o)
__device__ int   g_d2[1024];            // 512 - colsum(mask2)
__device__ int   g_pos1[1024], g_perm1[1024], g_L0p[1024];
__device__ int   g_pos2[1024], g_perm2[1024], g_L1p[1024];
__device__ int   g_idp[1024];           // identity positions

__device__ __forceinline__ void pdl_wait() {
    asm volatile("griddepcontrol.wait;" ::: "memory");
}
__device__ __forceinline__ void pdl_launch_dependents() {
    asm volatile("griddepcontrol.launch_dependents;" ::: "memory");
}

__device__ __forceinline__ float tanh_fast(float x) {
    float r;
    asm("tanh.approx.f32 %0, %1;" : "=f"(r) : "f"(x));
    return r;
}
__device__ __forceinline__ unsigned long long pack2(float lo, float hi) {
    unsigned long long r;
    asm("mov.b64 %0, {%1, %2};" : "=l"(r) : "f"(lo), "f"(hi));
    return r;
}
__device__ __forceinline__ void unpack2(float& lo, float& hi, unsigned long long v) {
    asm("mov.b64 {%0, %1}, %2;" : "=f"(lo), "=f"(hi) : "l"(v));
}
__device__ __forceinline__ unsigned long long mul2(unsigned long long a, unsigned long long b) {
    unsigned long long r;
    asm("mul.rn.f32x2 %0, %1, %2;" : "=l"(r) : "l"(a), "l"(b));
    return r;
}
__device__ __forceinline__ unsigned long long fma2(unsigned long long a, unsigned long long b,
                                                   unsigned long long c) {
    unsigned long long r;
    asm("fma.rn.f32x2 %0, %1, %2, %3;" : "=l"(r) : "l"(a), "l"(b), "l"(c));
    return r;
}

// ---------------- phase 1: mask sums + zero + identity ----------------
// grid: [0,320) rowsums ; [320,352) d2 colsums ; [352,512) zero ; [512,516) id
__global__ void __launch_bounds__(256) phase1_kernel(
    const float* __restrict__ mask0, const float* __restrict__ mask1,
    const float* __restrict__ mask2, float4* __restrict__ outz) {
    int bid = blockIdx.x, tid = threadIdx.x;
    pdl_launch_dependents();   // no upstream deps; let phase2 CTAs spool up
    if (bid < 320) {
        int wrow = bid * 8 + (tid >> 5);      // 0..2559
        int lane = tid & 31;
        const float* row; int len; int* dst; int r;
        if (wrow < 1024)      { r = wrow;        row = mask0 + r * 512;  len = 512;  dst = g_rs0; }
        else if (wrow < 2048) { r = wrow - 1024; row = mask1 + r * 1024; len = 1024; dst = g_rs1; }
        else                  { r = wrow - 2048; row = mask2 + r * 1024; len = 1024; dst = g_rs2; }
        float s = 0.f;
        for (int c = lane; c < len; c += 32) s += row[c];
#pragma unroll
        for (int d = 16; d > 0; d >>= 1) s += __shfl_xor_sync(0xffffffffu, s, d);
        if (lane == 0) dst[r] = (int)(s + 0.5f);
        return;
    }
    if (bid < 352) {
        // d2 colsums: CTA c covers columns [32c, 32c+32); warp w sums rows [64w, 64w+64)
        __shared__ int part[8][32];
        int c = bid - 320;
        int w = tid >> 5, lane = tid & 31;
        int col = c * 32 + lane;
        int acc = 0;
        for (int r = 0; r < 64; ++r)
            acc += (int)(mask2[(w * 64 + r) * 1024 + col] + 0.5f);
        part[w][lane] = acc;
        __syncthreads();
        if (w == 0) {
            int s = 0;
#pragma unroll
            for (int q = 0; q < 8; ++q) s += part[q][lane];
            g_d2[col] = 512 - s;
        }
        return;
    }
    if (bid < 512) {
        int idx = (bid - 352) * 256 + tid;    // 40960 float4s
        float4 z = make_float4(0.f, 0.f, 0.f, 0.f);
        if (idx < 16384)      ((float4*)g_h1)[idx] = z;
        else if (idx < 32768) ((float4*)g_h2)[idx - 16384] = z;
        else if (idx < 40960) outz[idx - 32768] = z;
        return;
    }
    {
        int j = (bid - 512) * 256 + tid;
        if (j < 1024) g_idp[j] = j;
    }
}

// ---------------- phase 2: parallel deterministic rank sort ----------------
// grid 256 x 256thr; warp per element. CTAs [0,128): key=rs0 -> pos1/perm1/L0p.
// CTAs [128,256): key=d2 -> pos2/perm2/L1p.
__global__ void __launch_bounds__(256) phase2_kernel() {
    int w = threadIdx.x >> 5, lane = threadIdx.x & 31;
    bool second = blockIdx.x >= 128;
    int t = (blockIdx.x & 127) * 8 + w;   // 0..1023
    pdl_wait();                 // rs0/d2/rs1 from phase1
    pdl_launch_dependents();
    const int* keys = second ? g_d2 : g_rs0;
    int k = keys[t];
    int r = 0;
    for (int h = lane; h < 1024; h += 32) {
        int kh = keys[h];
        r += (kh < k) || (kh == k && h < t);
    }
#pragma unroll
    for (int d = 16; d > 0; d >>= 1) r += __shfl_xor_sync(0xffffffffu, r, d);
    if (lane == 0) {
        if (!second) {
            g_pos1[t] = r;
            g_perm1[r] = t;
            g_L0p[r] = k;              // sorted row length = its d1
        } else {
            g_pos2[t] = r;
            g_perm2[r] = t;
            g_L1p[r] = g_rs1[t];       // prefix length in sorted-d1 input space
        }
    }
}

// ---------------- phase 3: permuted MW (row-major) + cond GEMVs --------------
// grid: [0,512) L0 direct ; [512,640) L1 smem-permute ; [640,704) L2 smem-permute
//       [704,2240) cond GEMVs (6*256)
__global__ void __launch_bounds__(256) phase3_kernel(
    const float* __restrict__ mask0, const float* __restrict__ W0,
    const float* __restrict__ mask1, const float* __restrict__ W1,
    const float* __restrict__ mask2, const float* __restrict__ W2,
    const float* __restrict__ u,
    const float* __restrict__ cw0, const float* __restrict__ cb0,
    const float* __restrict__ cw1, const float* __restrict__ cb1,
    const float* __restrict__ cw2, const float* __restrict__ cb2,
    const float* __restrict__ cw3, const float* __restrict__ cb3,
    const float* __restrict__ cw4, const float* __restrict__ cb4,
    const float* __restrict__ cw5, const float* __restrict__ cb5) {
    __shared__ float sh[9216];   // 8 rows x 1024 + 1024-int perm (aliased) / us
    int bid = blockIdx.x, tid = threadIdx.x;
    pdl_wait();                  // perms/pos from phase2
    pdl_launch_dependents();

    if (bid < 512) {
        // L0: MWp0[o'][i] = (mask0*W0)[perm1[o']][i] — fully coalesced
        int idx = bid * 256 + tid;           // f4 index: [1024 rows][128 f4]
        int o = idx >> 7, i4 = idx & 127;
        int srow = g_perm1[o];
        float4 mv = ((const float4*)(mask0 + srow * 512))[i4];
        float4 wv = ((const float4*)(W0 + srow * 512))[i4];
        ((float4*)g_MWp0)[idx] =
            make_float4(mv.x * wv.x, mv.y * wv.y, mv.z * wv.z, mv.w * wv.w);
        return;
    }
    if (bid < 704) {
        // L1 / L2: row gather (coalesced) + column permute via smem
        bool isL1 = bid < 640;
        int rb = isL1 ? (bid - 512) * 8 : (bid - 640) * 8;
        float* rowbuf = sh;
        int* ps = (int*)(sh + 8192);
        const int* permC = isL1 ? g_perm1 : g_perm2;   // column permutation
        for (int k = tid; k < 1024; k += 256) ps[k] = permC[k];
        for (int k = tid; k < 2048; k += 256) {        // 8 rows x 256 f4
            int r = k >> 8, i4 = k & 255;
            int srow = isL1 ? g_perm2[rb + r] : (rb + r);
            const float* mrow = (isL1 ? mask1 : mask2) + (size_t)srow * 1024;
            const float* wrow = (isL1 ? W1 : W2) + (size_t)srow * 1024;
            float4 mv = ((const float4*)mrow)[i4];
            float4 wv = ((const float4*)wrow)[i4];
            *(float4*)&rowbuf[r * 1024 + i4 * 4] =
                make_float4(mv.x * wv.x, mv.y * wv.y, mv.z * wv.z, mv.w * wv.w);
        }
        __syncthreads();
        float* dst = isL1 ? g_MWp1 : g_MWp2;
        for (int k = tid; k < 8192; k += 256) {
            int r = k >> 10, i = k & 1023;
            dst[(size_t)(rb + r) * 1024 + i] = rowbuf[r * 1024 + ps[i]];
        }
        return;
    }
    // ---- cond GEMVs with permuted destinations ----
    {
        float* us = sh;  // 64*65 floats
        int cbid = bid - 704;
        int jblk = cbid & 255;
        int which = cbid >> 8;  // 0..5
        for (int k = tid; k < 64 * 64; k += 256)
            us[(k >> 6) * 65 + (k & 63)] = u[k];
        __syncthreads();

        const float* w; const float* bias; const int* pos;
        int J; float scale; float* dstp;
        switch (which) {
            case 0:  w = cw0; bias = cb0; J = 512;  scale = 1.0f; dstp = g_f1a;          pos = g_idp;  break;
            case 1:  w = cw1; bias = cb1; J = 1024; scale = 0.5f; dstp = g_f2a;          pos = g_pos1; break;
            case 2:  w = cw2; bias = cb2; J = 1024; scale = 1.0f; dstp = g_f1a + 65536;  pos = g_pos1; break;
            case 3:  w = cw3; bias = cb3; J = 1024; scale = 0.5f; dstp = g_f2a + 65536;  pos = g_pos2; break;
            case 4:  w = cw4; bias = cb4; J = 1024; scale = 1.0f; dstp = g_f1a + 131072; pos = g_pos2; break;
            default: w = cw5; bias = cb5; J = 512;  scale = 0.5f; dstp = g_f2a + 131072; pos = g_idp;  break;
        }
        int b = tid & 63;
        int jj = tid >> 6;
        int j = jblk * 4 + jj;
        if (j >= J) return;
        const float* wr = w + j * 64;
        float acc = 0.0f;
#pragma unroll
        for (int c = 0; c < 64; ++c)
            acc = __fmaf_rn(wr[c], us[b * 65 + c], acc);
        dstp[b * J + pos[j]] = (acc + bias[j]) * scale;
    }
}

// ---------------- main layer kernel ----------------
// CTA = 32 outputs x 16 batches (8 f32x2 pairs) x ISEG=16 inputs (R8/R11 shape).
// Thread: output oBase+tx, pairs ty and ty+4 (4 scalar tanh chains in flight).
// FULL compile-time inner loop: MW zeros beyond the mask prefix make boundary
// iterations contribute exactly 0. Dead tiles exit early (after pdl wait).
// grid (O/32, 4, NS); split-K accumulated into hdst via atomicAdd (RED).
template <int I, int O, int NS>
__global__ void __launch_bounds__(128) layer_kernel(
    const float* __restrict__ xsrc,
    const float* __restrict__ f1, const float* __restrict__ f2,
    const float* __restrict__ MW, const int* __restrict__ Lp,
    float* __restrict__ hdst) {
    constexpr int ISEG = I / NS;      // 16
    constexpr int NPAIRS = ISEG / 2;  // 8

    __shared__ float2 MW2s[NPAIRS][32];            // [ii-pair][o]
    __shared__ unsigned long long fps[8][ISEG];    // packed f1 batch-pairs
    __shared__ unsigned long long xps[8][ISEG];    // packed x  batch-pairs

    int tx = threadIdx.x, ty = threadIdx.y;
    int tid = ty * 32 + tx;
    int oBase = blockIdx.x * 32;
    int bBase = blockIdx.y * 16;
    int iBase = blockIdx.z * ISEG;

    pdl_wait();                  // MW/f1/f2/xsrc from predecessors
    pdl_launch_dependents();

    if (iBase >= Lp[oBase + 31]) return;  // rows ascending => whole tile masked

    // stage MW as ii-pairs: 32 o x 4 float4, exactly one per thread
    {
        int o = tid >> 2, i4 = tid & 3;   // ISEG/4 = 4
        float4 v = *(const float4*)(MW + (size_t)(oBase + o) * I + iBase + i4 * 4);
        MW2s[i4 * 2 + 0][o] = make_float2(v.x, v.y);
        MW2s[i4 * 2 + 1][o] = make_float2(v.z, v.w);
    }
    // stage packed (f1, x): 8 pairs x 16 ii = 128 items, one per thread
    {
        int pr = tid >> 4, ii = tid & 15;
        int b = bBase + 2 * pr;
        int gi = iBase + ii;
        fps[pr][ii] = pack2(f1[b * I + gi], f1[(b + 1) * I + gi]);
        xps[pr][ii] = pack2(xsrc[b * I + gi], xsrc[(b + 1) * I + gi]);
    }

    int o = oBase + tx;
    unsigned long long f2p[2], acc[2];
#pragma unroll
    for (int r = 0; r < 2; ++r) {
        int b = bBase + 2 * (ty + 4 * r);
        f2p[r] = pack2(f2[b * O + o], f2[(b + 1) * O + o]);
        acc[r] = 0ULL;
    }
    const unsigned long long H = 0x3f0000003f000000ULL;  // {0.5f, 0.5f}

    __syncthreads();

#pragma unroll
    for (int p = 0; p < NPAIRS; ++p) {
        float2 mw = MW2s[p][tx];                       // one LDS.64 per 2 ii
        unsigned long long mwd0 = pack2(mw.x, mw.x);
        unsigned long long mwd1 = pack2(mw.y, mw.y);
#pragma unroll
        for (int r = 0; r < 2; ++r) {
            int pr = ty + 4 * r;
            ulonglong2 fq = *(const ulonglong2*)&fps[pr][2 * p];  // LDS.128
            ulonglong2 xq = *(const ulonglong2*)&xps[pr][2 * p];  // LDS.128
            float za, zb;
            unsigned long long z0 = mul2(fq.x, f2p[r]);
            unpack2(za, zb, z0);
            unsigned long long t0 = pack2(tanh_fast(za), tanh_fast(zb));
            unsigned long long s0 = fma2(t0, H, H);
            acc[r] = fma2(s0, mul2(mwd0, xq.x), acc[r]);
            unsigned long long z1 = mul2(fq.y, f2p[r]);
            unpack2(za, zb, z1);
            unsigned long long t1 = pack2(tanh_fast(za), tanh_fast(zb));
            unsigned long long s1 = fma2(t1, H, H);
            acc[r] = fma2(s1, mul2(mwd1, xq.y), acc[r]);
        }
    }

#pragma unroll
    for (int r = 0; r < 2; ++r) {
        int b = bBase + 2 * (ty + 4 * r);
        float a0, a1;
        unpack2(a0, a1, acc[r]);
        atomicAdd(hdst + b * O + o, a0);
        atomicAdd(hdst + (b + 1) * O + o, a1);
    }
}

// host helper: launch with programmatic stream serialization (PDL)
template <typename F, typename... Args>
static void launch_pdl(dim3 grid, dim3 block, F func, Args... args) {
    cudaLaunchConfig_t cfg = {};
    cfg.gridDim = grid;
    cfg.blockDim = block;
    cfg.dynamicSmemBytes = 0;
    cfg.stream = 0;
    cudaLaunchAttribute attr[1];
    attr[0].id = cudaLaunchAttributeProgrammaticStreamSerialization;
    attr[0].val.programmaticStreamSerializationAllowed = 1;
    cfg.attrs = attr;
    cfg.numAttrs = 1;
    cudaLaunchKernelEx(&cfg, func, args...);
}

extern "C" void kernel_launch(void* const* d_in, const int* in_sizes, int n_in,
                              void* d_out, int out_size) {
    const float* x     = (const float*)d_in[0];
    const float* u     = (const float*)d_in[1];
    const float* mask0 = (const float*)d_in[2];
    const float* mask1 = (const float*)d_in[3];
    const float* mask2 = (const float*)d_in[4];
    const float* W0    = (const float*)d_in[5];
    const float* W1    = (const float*)d_in[6];
    const float* W2    = (const float*)d_in[7];
    const float* a0_w  = (const float*)d_in[8];
    const float* a0_b  = (const float*)d_in[9];
    const float* b0_w  = (const float*)d_in[10];
    const float* b0_b  = (const float*)d_in[11];
    const float* a1_w  = (const float*)d_in[12];
    const float* a1_b  = (const float*)d_in[13];
    const float* b1_w  = (const float*)d_in[14];
    const float* b1_b  = (const float*)d_in[15];
    const float* a2_w  = (const float*)d_in[16];
    const float* a2_b  = (const float*)d_in[17];
    const float* b2_w  = (const float*)d_in[18];
    const float* b2_b  = (const float*)d_in[19];
    float* out = (float*)d_out;

    float* pMW0; cudaGetSymbolAddress((void**)&pMW0, g_MWp0);
    float* pMW1; cudaGetSymbolAddress((void**)&pMW1, g_MWp1);
    float* pMW2; cudaGetSymbolAddress((void**)&pMW2, g_MWp2);
    float* pf1;  cudaGetSymbolAddress((void**)&pf1, g_f1a);
    float* pf2;  cudaGetSymbolAddress((void**)&pf2, g_f2a);
    float* ph1;  cudaGetSymbolAddress((void**)&ph1, g_h1);
    float* ph2;  cudaGetSymbolAddress((void**)&ph2, g_h2);
    int* pL0;    cudaGetSymbolAddress((void**)&pL0, g_L0p);
    int* pL1;    cudaGetSymbolAddress((void**)&pL1, g_L1p);
    int* pL2;    cudaGetSymbolAddress((void**)&pL2, g_rs2);

    // 1) mask sums (rowsums + d2 colsums) + zero + identity
    phase1_kernel<<<516, 256>>>(mask0, mask1, mask2, (float4*)out);

    // 2) parallel degree-rank sort (deterministic) — PDL chained
    launch_pdl(dim3(256), dim3(256), phase2_kernel);

    // 3) permuted row-major MW + cond GEMVs (permuted dst) — PDL chained
    launch_pdl(dim3(2240), dim3(256), phase3_kernel,
        mask0, W0, mask1, W1, mask2, W2, u,
        a0_w, a0_b, b0_w, b0_b,
        a1_w, a1_b, b1_w, b1_b,
        a2_w, a2_b, b2_w, b2_b);

    // 4) layer 0: x -> h1 (sorted space) ; NS=32, ISEG=16
    launch_pdl(dim3(32, 4, 32), dim3(32, 4), &layer_kernel<512, 1024, 32>,
        x, (const float*)pf1, (const float*)pf2, (const float*)pMW0,
        (const int*)pL0, ph1);

    // 5) layer 1: h1 -> h2 (sorted space) ; NS=64, ISEG=16
    launch_pdl(dim3(32, 4, 64), dim3(32, 4), &layer_kernel<1024, 1024, 64>,
        (const float*)ph1, (const float*)(pf1 + 65536), (const float*)(pf2 + 65536),
        (const float*)pMW1, (const int*)pL1, ph2);

    // 6) layer 2: h2 -> d_out (natural rows) ; NS=64, ISEG=16
    launch_pdl(dim3(16, 4, 64), dim3(32, 4), &layer_kernel<1024, 512, 64>,
        (const float*)ph2, (const float*)(pf1 + 131072), (const float*)(pf2 + 131072),
        (const float*)pMW2, (const int*)pL2, out);
}